// round 10
// baseline (speedup 1.0000x reference)
#include <cuda_runtime.h>
#include <math.h>

#define D 4
#define H 16
#define DH 64

#define N_MAX 65536

// Scratch (device globals). 256B alignment -> whole 128B lines per node.
__device__ __align__(256) float4 g_xf4[N_MAX * (DH / 4)];    // transformed features
__device__ __align__(256) float4 g_uv4[N_MAX * 8];           // per-node u(16), v(16)
__device__ __align__(256) float4 g_agg4[N_MAX * (DH / 4)];   // message aggregation
__device__ float  g_deg[N_MAX];   // starts 0; k_dis consumes (+1 self loop), resets to 0
__device__ float  g_dis[N_MAX];   // (1+deg)^{-1/2}

// ---------------------------------------------------------------------------
// K1 (fused): blocks [0, TB): node transform + u/v projection (smem-staged);
// blocks [TB, TB+DB): source-node out-degree atomics.
// ---------------------------------------------------------------------------
#define XSTR 68   // padded node row stride (floats): float4-aligned, conflict-free

__global__ void __launch_bounds__(256) k_transform_deg_uv(
        const float* __restrict__ x,
        const float* __restrict__ W1,
        const float* __restrict__ W2,
        const float* __restrict__ m1w,
        const int* __restrict__ ei,
        int N, int E, int TB) {
    __shared__ float W1s[16];
    __shared__ __align__(16) float W2s[256];
    __shared__ __align__(16) float xs[64 * XSTR];   // 64 nodes staged / xf overwrite
    // uv weights at row (q*4 + part): part-stride 68 = 4 (mod 32) -> conflict-free.
    __shared__ __align__(16) float wt[32 * XSTR];

    int tid = threadIdx.x;

    if (blockIdx.x >= TB) {
        int e = (blockIdx.x - TB) * 256 + tid;
        if (e < E) atomicAdd(&g_deg[ei[e]], 1.0f);
        return;
    }

    if (tid < 16) W1s[tid] = W1[tid];
    for (int i = tid; i < 256; i += 256) W2s[i] = W2[i];
    for (int i = tid; i < 32 * 64; i += 256) {
        int oi = i >> 6;
        int k  = i & 63;
        int part = oi >> 3;
        int q    = oi & 7;
        float wv = (oi < 16) ? m1w[oi * 128 + k]
                             : m1w[(oi - 16) * 128 + 64 + k];
        wt[(q * 4 + part) * XSTR + k] = wv;
    }

    int nbase = blockIdx.x * 64;
    int navail = N - nbase;
    int nloc = navail >= 64 ? 64 : navail;
    int total = nloc * 64;
#pragma unroll 4
    for (int i = tid; i < total; i += 256) {
        int nl = i >> 6;
        int k  = i & 63;
        xs[nl * XSTR + k] = x[(size_t)nbase * 64 + i];
    }
    __syncthreads();

    int nl = tid >> 2;           // local node 0..63
    int d  = tid & 3;
    int n  = nbase + nl;

    float4 o4[4];
    if (n < N) {
        const float* xr = xs + nl * XSTR;
        float tf[16];
#pragma unroll
        for (int f = 0; f < 16; ++f) tf[f] = 0.f;
#pragma unroll
        for (int dd = 0; dd < 4; ++dd) {
            float w = W1s[dd * 4 + d];
#pragma unroll
            for (int f = 0; f < 16; ++f) tf[f] += w * xr[dd * 16 + f];
        }
        const float4* W2s4 = (const float4*)W2s;
#pragma unroll
        for (int g4 = 0; g4 < 4; ++g4) o4[g4] = make_float4(0.f, 0.f, 0.f, 0.f);
#pragma unroll
        for (int f = 0; f < 16; ++f) {
            float tv = tf[f];
#pragma unroll
            for (int g4 = 0; g4 < 4; ++g4) {
                float4 wv = W2s4[f * 4 + g4];
                o4[g4].x += tv * wv.x;
                o4[g4].y += tv * wv.y;
                o4[g4].z += tv * wv.z;
                o4[g4].w += tv * wv.w;
            }
        }
    }
    __syncthreads();   // all xs reads done before overwrite

    if (n < N) {
        float4* xf4  = g_xf4  + (size_t)n * 16 + d * 4;
        float4* agg4 = g_agg4 + (size_t)n * 16 + d * 4;
        float4* xrow = (float4*)(xs + nl * XSTR) + d * 4;
#pragma unroll
        for (int g4 = 0; g4 < 4; ++g4) {
            xf4[g4]  = o4[g4];
            xrow[g4] = o4[g4];
            agg4[g4] = make_float4(0.f, 0.f, 0.f, 0.f);
        }
    }
    __syncthreads();

    // ---- uv: 128 threads, each computes 8 outputs for TWO nodes ----
    if (tid < 128) {
        int part = tid & 3;
        int nb   = tid >> 2;
        int n0 = nbase + nb;
        int n1 = nbase + nb + 32;
        bool v0 = (n0 < N);
        bool v1 = (n1 < N);

        const float4* xa4 = (const float4*)(xs + nb * XSTR);
        const float4* xb4 = (const float4*)(xs + (nb + 32) * XSTR);

        float acc0[8], acc1[8];
#pragma unroll
        for (int q = 0; q < 8; ++q) { acc0[q] = 0.f; acc1[q] = 0.f; }

#pragma unroll
        for (int k4 = 0; k4 < 16; ++k4) {
            float4 xa = v0 ? xa4[k4] : make_float4(0.f, 0.f, 0.f, 0.f);
            float4 xb = v1 ? xb4[k4] : make_float4(0.f, 0.f, 0.f, 0.f);
#pragma unroll
            for (int q = 0; q < 8; ++q) {
                const float4 wv = *(const float4*)(wt + (q * 4 + part) * XSTR + k4 * 4);
                acc0[q] += wv.x * xa.x + wv.y * xa.y + wv.z * xa.z + wv.w * xa.w;
                acc1[q] += wv.x * xb.x + wv.y * xb.y + wv.z * xb.z + wv.w * xb.w;
            }
        }
        if (v0) {
            float4* uvp = (float4*)((float*)(g_uv4 + (size_t)n0 * 8) + part * 8);
            uvp[0] = make_float4(acc0[0], acc0[1], acc0[2], acc0[3]);
            uvp[1] = make_float4(acc0[4], acc0[5], acc0[6], acc0[7]);
        }
        if (v1) {
            float4* uvp = (float4*)((float*)(g_uv4 + (size_t)n1 * 8) + part * 8);
            uvp[0] = make_float4(acc1[0], acc1[1], acc1[2], acc1[3]);
            uvp[1] = make_float4(acc1[4], acc1[5], acc1[6], acc1[7]);
        }
    }
}

// ---------------------------------------------------------------------------
// K2: dis = rsqrt(1 + deg); reset deg -> 0 for next graph replay.
// ---------------------------------------------------------------------------
__global__ void k_dis(int N) {
    int n = blockIdx.x * blockDim.x + threadIdx.x;
    if (n < N) {
        g_dis[n] = rsqrtf(1.0f + g_deg[n]);
        g_deg[n] = 0.f;
    }
}

// ---------------------------------------------------------------------------
// MGS QR of A = I + strictly-lower(params). Q[col][row].
// ---------------------------------------------------------------------------
__device__ __forceinline__ void qr4(const float p[6], float Q[4][4]) {
    const float a[4][4] = {
        {1.f,  p[0], p[1], p[3]},
        {0.f,  1.f,  p[2], p[4]},
        {0.f,  0.f,  1.f,  p[5]},
        {0.f,  0.f,  0.f,  1.f }};
#pragma unroll
    for (int c = 0; c < 4; ++c) {
        float v0 = a[c][0], v1 = a[c][1], v2 = a[c][2], v3 = a[c][3];
#pragma unroll
        for (int j = 0; j < c; ++j) {
            float r = v0 * Q[j][0] + v1 * Q[j][1] + v2 * Q[j][2] + v3 * Q[j][3];
            v0 -= r * Q[j][0];
            v1 -= r * Q[j][1];
            v2 -= r * Q[j][2];
            v3 -= r * Q[j][3];
        }
        float inv = rsqrtf(v0 * v0 + v1 * v1 + v2 * v2 + v3 * v3);
        Q[c][0] = v0 * inv; Q[c][1] = v1 * inv; Q[c][2] = v2 * inv; Q[c][3] = v3 * inv;
    }
}

__device__ __forceinline__ void red4(float4* addr, float4 v) {
    asm volatile("red.global.add.v4.f32 [%0], {%1, %2, %3, %4};"
                 :: "l"(addr), "f"(v.x), "f"(v.y), "f"(v.z), "f"(v.w)
                 : "memory");
}

// ---------------------------------------------------------------------------
// K3: phase-cooperative edge kernel. Now 10 blocks/SM: h streamed from smem
// in the mlp2 loop (no h_all[32] register array) to fit the 51-reg cap.
// ---------------------------------------------------------------------------
#define ROWS 36  // floats per edge row: 32 + pad; 144B = 16B-aligned, bank-clean

__global__ void __launch_bounds__(128, 10) k_edge(
        const int* __restrict__ ei,
        const float* __restrict__ b1,
        const float* __restrict__ w2,
        const float* __restrict__ b2,
        int E) {
    __shared__ __align__(16) float s_h[4][32 * ROWS];
    __shared__ float b1s[16];
    __shared__ float w2p[128];   // w2p[t*8+c], padded
    __shared__ float b2s[8];

    int tid = threadIdx.x;
    if (tid < 16) b1s[tid] = b1[tid];
    if (tid < 128) w2p[tid] = ((tid & 7) < 6) ? w2[(tid & 7) * 16 + (tid >> 3)] : 0.f;
    if (tid < 6)  b2s[tid] = b2[tid];
    __syncthreads();

    int lane = tid & 31;
    int w    = tid >> 5;
    float* Hs = s_h[w];

    int ebase = (blockIdx.x * 4 + w) * 32;
    int eg = ebase + lane;

    int rj = 0, ci = 0;
    if (eg < E) {
        rj = ei[eg];
        ci = ei[E + eg];
    }
    float s = g_dis[ci] * g_dis[rj];
    float b1r = b1s[lane & 15];

    // ---- Phase A: gather + fused relu-combine -> edge-major smem ----
    const float* uvbase = (const float*)g_uv4;
#pragma unroll 4
    for (int e = 0; e < 32; ++e) {
        int rje = __shfl_sync(0xffffffffu, rj, e);
        int cie = __shfl_sync(0xffffffffu, ci, e);
        float ui = __ldg(uvbase + (size_t)cie * 32 + lane);
        float uj = __ldg(uvbase + (size_t)rje * 32 + lane);
        float h = fmaxf(ui + __shfl_xor_sync(0xffffffffu, uj, 16) + b1r, 0.f);
        Hs[e * ROWS + lane] = h;
    }
    __syncwarp();

    // ---- Phase B: thread-per-edge mlp2 + QR + M (h streamed from smem) ----
    {
        const float4* hrow = (const float4*)(Hs + lane * ROWS);

        float pve[6], pue[6];
#pragma unroll
        for (int c = 0; c < 6; ++c) { pve[c] = b2s[c]; pue[c] = b2s[c]; }
#pragma unroll
        for (int q = 0; q < 4; ++q) {
            float4 hv4 = hrow[q];        // hve[4q .. 4q+3]
            float4 hu4 = hrow[4 + q];    // hue[4q .. 4q+3]
#pragma unroll
            for (int r = 0; r < 4; ++r) {
                int t = q * 4 + r;
                float hv = (r == 0) ? hv4.x : (r == 1) ? hv4.y : (r == 2) ? hv4.z : hv4.w;
                float hu = (r == 0) ? hu4.x : (r == 1) ? hu4.y : (r == 2) ? hu4.z : hu4.w;
                float4 wA = *(const float4*)(w2p + t * 8);
                float4 wB = *(const float4*)(w2p + t * 8 + 4);
                pve[0] += wA.x * hv;  pue[0] += wA.x * hu;
                pve[1] += wA.y * hv;  pue[1] += wA.y * hu;
                pve[2] += wA.z * hv;  pue[2] += wA.z * hu;
                pve[3] += wA.w * hv;  pue[3] += wA.w * hu;
                pve[4] += wB.x * hv;  pue[4] += wB.x * hu;
                pve[5] += wB.y * hv;  pue[5] += wB.y * hu;
            }
        }

        float Qv[4][4], Qu[4][4];
        qr4(pve, Qv);
        qr4(pue, Qu);

        float4* Mrow = (float4*)(Hs + lane * ROWS);
#pragma unroll
        for (int a = 0; a < 4; ++a) {
            float4 m;
            m.x = s * (Qv[a][0] * Qu[0][0] + Qv[a][1] * Qu[0][1] + Qv[a][2] * Qu[0][2] + Qv[a][3] * Qu[0][3]);
            m.y = s * (Qv[a][0] * Qu[1][0] + Qv[a][1] * Qu[1][1] + Qv[a][2] * Qu[1][2] + Qv[a][3] * Qu[1][3]);
            m.z = s * (Qv[a][0] * Qu[2][0] + Qv[a][1] * Qu[2][1] + Qv[a][2] * Qu[2][2] + Qv[a][3] * Qu[2][3]);
            m.w = s * (Qv[a][0] * Qu[3][0] + Qv[a][1] * Qu[3][1] + Qv[a][2] * Qu[3][2] + Qv[a][3] * Qu[3][3]);
            Mrow[a] = m;
        }
    }
    __syncwarp();

    // ---- Phase C: 16 lanes per edge, 2 edges per step ----
    int half = lane >> 4;
    int sub  = lane & 15;
    int a    = sub >> 2;
    int h4   = sub & 3;

#pragma unroll 4
    for (int it = 0; it < 16; ++it) {
        int e = it * 2 + half;
        int rje = __shfl_sync(0xffffffffu, rj, e);
        int cie = __shfl_sync(0xffffffffu, ci, e);

        const float4* xj4 = g_xf4 + (size_t)rje * 16;
        float4 x0 = __ldg(xj4 + 0 * 4 + h4);
        float4 x1 = __ldg(xj4 + 1 * 4 + h4);
        float4 x2 = __ldg(xj4 + 2 * 4 + h4);
        float4 x3 = __ldg(xj4 + 3 * 4 + h4);

        float4 mr = *(const float4*)(Hs + e * ROWS + a * 4);

        float4 m;
        m.x = mr.x * x0.x + mr.y * x1.x + mr.z * x2.x + mr.w * x3.x;
        m.y = mr.x * x0.y + mr.y * x1.y + mr.z * x2.y + mr.w * x3.y;
        m.z = mr.x * x0.z + mr.y * x1.z + mr.z * x2.z + mr.w * x3.z;
        m.w = mr.x * x0.w + mr.y * x1.w + mr.z * x2.w + mr.w * x3.w;

        if (ebase + e < E)
            red4(g_agg4 + (size_t)cie * 16 + a * 4 + h4, m);
    }
}

// ---------------------------------------------------------------------------
// K4: out = (1 + tanh(eps_d)) * x - elu(agg + xf/deg)   (float4 per thread)
// ---------------------------------------------------------------------------
__global__ void k_final(const float* __restrict__ x,
                        const float* __restrict__ eps,
                        float* __restrict__ out, int N) {
    int i = blockIdx.x * blockDim.x + threadIdx.x;   // float4 index
    if (i >= N * 16) return;
    int n = i >> 4;
    int d = (i >> 2) & 3;
    float coeff = 1.0f + tanhf(__ldg(eps + d));
    float dsv = g_dis[n];
    float ds2 = dsv * dsv;

    float4 ag = g_agg4[i];
    float4 xf = g_xf4[i];
    float4 xv = ((const float4*)x)[i];

    float a0 = ag.x + ds2 * xf.x;
    float a1 = ag.y + ds2 * xf.y;
    float a2 = ag.z + ds2 * xf.z;
    float a3 = ag.w + ds2 * xf.w;

    float4 o;
    o.x = coeff * xv.x - (a0 > 0.f ? a0 : expm1f(a0));
    o.y = coeff * xv.y - (a1 > 0.f ? a1 : expm1f(a1));
    o.z = coeff * xv.z - (a2 > 0.f ? a2 : expm1f(a2));
    o.w = coeff * xv.w - (a3 > 0.f ? a3 : expm1f(a3));
    ((float4*)out)[i] = o;
}

// ---------------------------------------------------------------------------
extern "C" void kernel_launch(void* const* d_in, const int* in_sizes, int n_in,
                              void* d_out, int out_size) {
    const float* x   = (const float*)d_in[0];
    const int*   ei  = (const int*)d_in[1];   // int32 (JAX x64 disabled)
    const float* W1  = (const float*)d_in[2];
    const float* W2  = (const float*)d_in[3];
    const float* eps = (const float*)d_in[4];
    const float* m1w = (const float*)d_in[5];
    const float* m1b = (const float*)d_in[6];
    const float* m2w = (const float*)d_in[7];
    const float* m2b = (const float*)d_in[8];

    int N = in_sizes[0] / DH;
    int E = in_sizes[1] / 2;

    int TB = (N + 63) / 64;          // transform blocks (64 nodes each)
    int DB = (E + 255) / 256;        // degree blocks

    k_transform_deg_uv<<<TB + DB, 256>>>(x, W1, W2, m1w, ei, N, E, TB);
    k_dis<<<(N + 255) / 256, 256>>>(N);
    k_edge<<<(E + 127) / 128, 128>>>(ei, m1b, m2w, m2b, E);
    k_final<<<(N * 16 + 255) / 256, 256>>>(x, eps, (float*)d_out, N);
}

// round 11
// speedup vs baseline: 1.0184x; 1.0184x over previous
#include <cuda_runtime.h>
#include <math.h>

#define D 4
#define H 16
#define DH 64

#define N_MAX 65536

// Scratch (device globals). 256B alignment -> whole 128B lines per node.
__device__ __align__(256) float4 g_xf4[N_MAX * (DH / 4)];    // transformed features
__device__ __align__(256) float4 g_uv4[N_MAX * 8];           // per-node u(16), v(16)
__device__ __align__(256) float4 g_agg4[N_MAX * (DH / 4)];   // message aggregation
__device__ float  g_deg[N_MAX];   // starts 0; K1 accumulates; k_final resets to 0

// ---------------------------------------------------------------------------
// K1 (fused): blocks [0, TB): node transform + u/v projection (smem-staged);
// blocks [TB, TB+DB): source-node out-degree atomics.
// ---------------------------------------------------------------------------
#define XSTR 68   // padded node row stride (floats): float4-aligned, conflict-free

__global__ void __launch_bounds__(256) k_transform_deg_uv(
        const float* __restrict__ x,
        const float* __restrict__ W1,
        const float* __restrict__ W2,
        const float* __restrict__ m1w,
        const int* __restrict__ ei,
        int N, int E, int TB) {
    __shared__ float W1s[16];
    __shared__ __align__(16) float W2s[256];
    __shared__ __align__(16) float xs[64 * XSTR];   // 64 nodes staged / xf overwrite
    // uv weights at row (q*4 + part): part-stride 68 = 4 (mod 32) -> conflict-free.
    __shared__ __align__(16) float wt[32 * XSTR];

    int tid = threadIdx.x;

    if (blockIdx.x >= TB) {
        int e = (blockIdx.x - TB) * 256 + tid;
        if (e < E) atomicAdd(&g_deg[ei[e]], 1.0f);
        return;
    }

    if (tid < 16) W1s[tid] = W1[tid];
    for (int i = tid; i < 256; i += 256) W2s[i] = W2[i];
    for (int i = tid; i < 32 * 64; i += 256) {
        int oi = i >> 6;
        int k  = i & 63;
        int part = oi >> 3;
        int q    = oi & 7;
        float wv = (oi < 16) ? m1w[oi * 128 + k]
                             : m1w[(oi - 16) * 128 + 64 + k];
        wt[(q * 4 + part) * XSTR + k] = wv;
    }

    int nbase = blockIdx.x * 64;
    int navail = N - nbase;
    int nloc = navail >= 64 ? 64 : navail;
    int total = nloc * 64;
#pragma unroll 4
    for (int i = tid; i < total; i += 256) {
        int nl = i >> 6;
        int k  = i & 63;
        xs[nl * XSTR + k] = x[(size_t)nbase * 64 + i];
    }
    __syncthreads();

    int nl = tid >> 2;           // local node 0..63
    int d  = tid & 3;
    int n  = nbase + nl;

    float4 o4[4];
    if (n < N) {
        const float* xr = xs + nl * XSTR;
        float tf[16];
#pragma unroll
        for (int f = 0; f < 16; ++f) tf[f] = 0.f;
#pragma unroll
        for (int dd = 0; dd < 4; ++dd) {
            float w = W1s[dd * 4 + d];
#pragma unroll
            for (int f = 0; f < 16; ++f) tf[f] += w * xr[dd * 16 + f];
        }
        const float4* W2s4 = (const float4*)W2s;
#pragma unroll
        for (int g4 = 0; g4 < 4; ++g4) o4[g4] = make_float4(0.f, 0.f, 0.f, 0.f);
#pragma unroll
        for (int f = 0; f < 16; ++f) {
            float tv = tf[f];
#pragma unroll
            for (int g4 = 0; g4 < 4; ++g4) {
                float4 wv = W2s4[f * 4 + g4];
                o4[g4].x += tv * wv.x;
                o4[g4].y += tv * wv.y;
                o4[g4].z += tv * wv.z;
                o4[g4].w += tv * wv.w;
            }
        }
    }
    __syncthreads();   // all xs reads done before overwrite

    if (n < N) {
        float4* xf4  = g_xf4  + (size_t)n * 16 + d * 4;
        float4* agg4 = g_agg4 + (size_t)n * 16 + d * 4;
        float4* xrow = (float4*)(xs + nl * XSTR) + d * 4;
#pragma unroll
        for (int g4 = 0; g4 < 4; ++g4) {
            xf4[g4]  = o4[g4];
            xrow[g4] = o4[g4];
            agg4[g4] = make_float4(0.f, 0.f, 0.f, 0.f);
        }
    }
    __syncthreads();

    // ---- uv: 128 threads, each computes 8 outputs for TWO nodes ----
    if (tid < 128) {
        int part = tid & 3;
        int nb   = tid >> 2;
        int n0 = nbase + nb;
        int n1 = nbase + nb + 32;
        bool v0 = (n0 < N);
        bool v1 = (n1 < N);

        const float4* xa4 = (const float4*)(xs + nb * XSTR);
        const float4* xb4 = (const float4*)(xs + (nb + 32) * XSTR);

        float acc0[8], acc1[8];
#pragma unroll
        for (int q = 0; q < 8; ++q) { acc0[q] = 0.f; acc1[q] = 0.f; }

#pragma unroll
        for (int k4 = 0; k4 < 16; ++k4) {
            float4 xa = v0 ? xa4[k4] : make_float4(0.f, 0.f, 0.f, 0.f);
            float4 xb = v1 ? xb4[k4] : make_float4(0.f, 0.f, 0.f, 0.f);
#pragma unroll
            for (int q = 0; q < 8; ++q) {
                const float4 wv = *(const float4*)(wt + (q * 4 + part) * XSTR + k4 * 4);
                acc0[q] += wv.x * xa.x + wv.y * xa.y + wv.z * xa.z + wv.w * xa.w;
                acc1[q] += wv.x * xb.x + wv.y * xb.y + wv.z * xb.z + wv.w * xb.w;
            }
        }
        if (v0) {
            float4* uvp = (float4*)((float*)(g_uv4 + (size_t)n0 * 8) + part * 8);
            uvp[0] = make_float4(acc0[0], acc0[1], acc0[2], acc0[3]);
            uvp[1] = make_float4(acc0[4], acc0[5], acc0[6], acc0[7]);
        }
        if (v1) {
            float4* uvp = (float4*)((float*)(g_uv4 + (size_t)n1 * 8) + part * 8);
            uvp[0] = make_float4(acc1[0], acc1[1], acc1[2], acc1[3]);
            uvp[1] = make_float4(acc1[4], acc1[5], acc1[6], acc1[7]);
        }
    }
}

// ---------------------------------------------------------------------------
// MGS QR of A = I + strictly-lower(params). Q[col][row].
// ---------------------------------------------------------------------------
__device__ __forceinline__ void qr4(const float p[6], float Q[4][4]) {
    const float a[4][4] = {
        {1.f,  p[0], p[1], p[3]},
        {0.f,  1.f,  p[2], p[4]},
        {0.f,  0.f,  1.f,  p[5]},
        {0.f,  0.f,  0.f,  1.f }};
#pragma unroll
    for (int c = 0; c < 4; ++c) {
        float v0 = a[c][0], v1 = a[c][1], v2 = a[c][2], v3 = a[c][3];
#pragma unroll
        for (int j = 0; j < c; ++j) {
            float r = v0 * Q[j][0] + v1 * Q[j][1] + v2 * Q[j][2] + v3 * Q[j][3];
            v0 -= r * Q[j][0];
            v1 -= r * Q[j][1];
            v2 -= r * Q[j][2];
            v3 -= r * Q[j][3];
        }
        float inv = rsqrtf(v0 * v0 + v1 * v1 + v2 * v2 + v3 * v3);
        Q[c][0] = v0 * inv; Q[c][1] = v1 * inv; Q[c][2] = v2 * inv; Q[c][3] = v3 * inv;
    }
}

__device__ __forceinline__ void red4(float4* addr, float4 v) {
    asm volatile("red.global.add.v4.f32 [%0], {%1, %2, %3, %4};"
                 :: "l"(addr), "f"(v.x), "f"(v.y), "f"(v.z), "f"(v.w)
                 : "memory");
}

// ---------------------------------------------------------------------------
// K2: phase-cooperative edge kernel (round-9 winner). s computed directly
// from g_deg: s = rsqrt((1+deg_i)(1+deg_j)) — no separate dis pass/launch.
// ---------------------------------------------------------------------------
#define ROWS 36  // floats per edge row: 32 + pad; 144B = 16B-aligned, bank-clean

__global__ void __launch_bounds__(128, 8) k_edge(
        const int* __restrict__ ei,
        const float* __restrict__ b1,
        const float* __restrict__ w2,
        const float* __restrict__ b2,
        int E) {
    __shared__ __align__(16) float s_h[4][32 * ROWS];
    __shared__ float b1s[16];
    __shared__ float w2p[128];   // w2p[t*8+c], padded
    __shared__ float b2s[8];

    int tid = threadIdx.x;
    if (tid < 16) b1s[tid] = b1[tid];
    if (tid < 128) w2p[tid] = ((tid & 7) < 6) ? w2[(tid & 7) * 16 + (tid >> 3)] : 0.f;
    if (tid < 6)  b2s[tid] = b2[tid];
    __syncthreads();

    int lane = tid & 31;
    int w    = tid >> 5;
    float* Hs = s_h[w];

    int ebase = (blockIdx.x * 4 + w) * 32;
    int eg = ebase + lane;

    int rj = 0, ci = 0;
    if (eg < E) {
        rj = ei[eg];
        ci = ei[E + eg];
    }
    float s = rsqrtf((1.0f + g_deg[ci]) * (1.0f + g_deg[rj]));
    float b1r = b1s[lane & 15];

    // ---- Phase A: gather + fused relu-combine -> edge-major smem ----
    const float* uvbase = (const float*)g_uv4;
#pragma unroll 4
    for (int e = 0; e < 32; ++e) {
        int rje = __shfl_sync(0xffffffffu, rj, e);
        int cie = __shfl_sync(0xffffffffu, ci, e);
        float ui = __ldg(uvbase + (size_t)cie * 32 + lane);
        float uj = __ldg(uvbase + (size_t)rje * 32 + lane);
        float h = fmaxf(ui + __shfl_xor_sync(0xffffffffu, uj, 16) + b1r, 0.f);
        Hs[e * ROWS + lane] = h;
    }
    __syncwarp();

    // ---- Phase B: thread-per-edge mlp2 + QR + M ----
    {
        const float4* hrow = (const float4*)(Hs + lane * ROWS);
        float h_all[32];
#pragma unroll
        for (int q = 0; q < 8; ++q) {
            float4 v = hrow[q];
            h_all[q * 4 + 0] = v.x;
            h_all[q * 4 + 1] = v.y;
            h_all[q * 4 + 2] = v.z;
            h_all[q * 4 + 3] = v.w;
        }

        float pve[6], pue[6];
#pragma unroll
        for (int c = 0; c < 6; ++c) { pve[c] = b2s[c]; pue[c] = b2s[c]; }
#pragma unroll
        for (int t = 0; t < 16; ++t) {
            float4 wA = *(const float4*)(w2p + t * 8);
            float4 wB = *(const float4*)(w2p + t * 8 + 4);
            float hv = h_all[t];
            float hu = h_all[16 + t];
            pve[0] += wA.x * hv;  pue[0] += wA.x * hu;
            pve[1] += wA.y * hv;  pue[1] += wA.y * hu;
            pve[2] += wA.z * hv;  pue[2] += wA.z * hu;
            pve[3] += wA.w * hv;  pue[3] += wA.w * hu;
            pve[4] += wB.x * hv;  pue[4] += wB.x * hu;
            pve[5] += wB.y * hv;  pue[5] += wB.y * hu;
        }

        float Qv[4][4], Qu[4][4];
        qr4(pve, Qv);
        qr4(pue, Qu);

        float4* Mrow = (float4*)(Hs + lane * ROWS);
#pragma unroll
        for (int a = 0; a < 4; ++a) {
            float4 m;
            m.x = s * (Qv[a][0] * Qu[0][0] + Qv[a][1] * Qu[0][1] + Qv[a][2] * Qu[0][2] + Qv[a][3] * Qu[0][3]);
            m.y = s * (Qv[a][0] * Qu[1][0] + Qv[a][1] * Qu[1][1] + Qv[a][2] * Qu[1][2] + Qv[a][3] * Qu[1][3]);
            m.z = s * (Qv[a][0] * Qu[2][0] + Qv[a][1] * Qu[2][1] + Qv[a][2] * Qu[2][2] + Qv[a][3] * Qu[2][3]);
            m.w = s * (Qv[a][0] * Qu[3][0] + Qv[a][1] * Qu[3][1] + Qv[a][2] * Qu[3][2] + Qv[a][3] * Qu[3][3]);
            Mrow[a] = m;
        }
    }
    __syncwarp();

    // ---- Phase C: 16 lanes per edge, 2 edges per step ----
    int half = lane >> 4;
    int sub  = lane & 15;
    int a    = sub >> 2;
    int h4   = sub & 3;

#pragma unroll 4
    for (int it = 0; it < 16; ++it) {
        int e = it * 2 + half;
        int rje = __shfl_sync(0xffffffffu, rj, e);
        int cie = __shfl_sync(0xffffffffu, ci, e);

        const float4* xj4 = g_xf4 + (size_t)rje * 16;
        float4 x0 = __ldg(xj4 + 0 * 4 + h4);
        float4 x1 = __ldg(xj4 + 1 * 4 + h4);
        float4 x2 = __ldg(xj4 + 2 * 4 + h4);
        float4 x3 = __ldg(xj4 + 3 * 4 + h4);

        float4 mr = *(const float4*)(Hs + e * ROWS + a * 4);

        float4 m;
        m.x = mr.x * x0.x + mr.y * x1.x + mr.z * x2.x + mr.w * x3.x;
        m.y = mr.x * x0.y + mr.y * x1.y + mr.z * x2.y + mr.w * x3.y;
        m.z = mr.x * x0.z + mr.y * x1.z + mr.z * x2.z + mr.w * x3.z;
        m.w = mr.x * x0.w + mr.y * x1.w + mr.z * x2.w + mr.w * x3.w;

        if (ebase + e < E)
            red4(g_agg4 + (size_t)cie * 16 + a * 4 + h4, m);
    }
}

// ---------------------------------------------------------------------------
// K3: out = (1 + tanh(eps_d)) * x - elu(agg + xf/(1+deg)); resets deg -> 0.
// ---------------------------------------------------------------------------
__global__ void k_final(const float* __restrict__ x,
                        const float* __restrict__ eps,
                        float* __restrict__ out, int N) {
    int i = blockIdx.x * blockDim.x + threadIdx.x;   // float4 index
    if (i >= N * 16) return;
    int n = i >> 4;
    int d = (i >> 2) & 3;
    float coeff = 1.0f + tanhf(__ldg(eps + d));
    float degv = g_deg[n];
    float ds2 = 1.0f / (1.0f + degv);

    float4 ag = g_agg4[i];
    float4 xf = g_xf4[i];
    float4 xv = ((const float4*)x)[i];

    float a0 = ag.x + ds2 * xf.x;
    float a1 = ag.y + ds2 * xf.y;
    float a2 = ag.z + ds2 * xf.z;
    float a3 = ag.w + ds2 * xf.w;

    float4 o;
    o.x = coeff * xv.x - (a0 > 0.f ? a0 : expm1f(a0));
    o.y = coeff * xv.y - (a1 > 0.f ? a1 : expm1f(a1));
    o.z = coeff * xv.z - (a2 > 0.f ? a2 : expm1f(a2));
    o.w = coeff * xv.w - (a3 > 0.f ? a3 : expm1f(a3));
    ((float4*)out)[i] = o;

    if ((i & 15) == 0) g_deg[n] = 0.f;   // reset for next graph replay
}

// ---------------------------------------------------------------------------
extern "C" void kernel_launch(void* const* d_in, const int* in_sizes, int n_in,
                              void* d_out, int out_size) {
    const float* x   = (const float*)d_in[0];
    const int*   ei  = (const int*)d_in[1];   // int32 (JAX x64 disabled)
    const float* W1  = (const float*)d_in[2];
    const float* W2  = (const float*)d_in[3];
    const float* eps = (const float*)d_in[4];
    const float* m1w = (const float*)d_in[5];
    const float* m1b = (const float*)d_in[6];
    const float* m2w = (const float*)d_in[7];
    const float* m2b = (const float*)d_in[8];

    int N = in_sizes[0] / DH;
    int E = in_sizes[1] / 2;

    int TB = (N + 63) / 64;          // transform blocks (64 nodes each)
    int DB = (E + 255) / 256;        // degree blocks

    k_transform_deg_uv<<<TB + DB, 256>>>(x, W1, W2, m1w, ei, N, E, TB);
    k_edge<<<(E + 127) / 128, 128>>>(ei, m1b, m2w, m2b, E);
    k_final<<<(N * 16 + 255) / 256, 256>>>(x, eps, (float*)d_out, N);
}